// round 4
// baseline (speedup 1.0000x reference)
#include <cuda_runtime.h>
#include <cstdint>

#define N_NODES 50000
#define N_FEAT  128
#define HID     64
#define N_EDGES 1600000
#define LN_EPS  1e-5f

// ---------------- scratch (device globals; no allocation) ----------------
__device__ float g_h   [N_NODES * HID];   // RK4 state at step start
__device__ float g_hin [N_NODES * HID];   // current stage input
__device__ float g_kacc[N_NODES * HID];   // RK4 accumulator
__device__ float g_xp  [N_NODES * HID];   // hn @ W_pos^T
__device__ float g_xn  [N_NODES * HID];   // hn @ W_neg^T
__device__ float g_aggp[N_NODES * HID];   // pos aggregation
__device__ float g_aggn[N_NODES * HID];   // neg aggregation
__device__ int   g_degp[N_NODES];
__device__ int   g_degn[N_NODES];
__device__ float g_dinvp[N_NODES];
__device__ float g_dinvn[N_NODES];
__device__ float g_normp[N_EDGES];
__device__ float g_normn[N_EDGES];
__device__ int   g_is64;

// ---------------- helpers ----------------
__device__ __forceinline__ int ld_idx(const void* p, long long i, int is64) {
    if (is64) return (int)((const long long*)p)[i];
    return ((const int*)p)[i];
}

// Detect whether edge indices are int64 or int32 (indices are < 50000 >= 0,
// so for int64 every high 32-bit word is zero).
__global__ void k_detect(const void* eip) {
    const int* w = (const int*)eip;
    int ok = 1;
    for (int i = 0; i < 32; i++)
        if (w[2 * i + 1] != 0) ok = 0;
    g_is64 = ok;
}

__global__ void k_initdeg() {
    int i = blockIdx.x * blockDim.x + threadIdx.x;
    if (i < N_NODES) { g_degp[i] = 1; g_degn[i] = 1; }
}

__global__ void k_count(const void* eip, const void* ein) {
    long long i = (long long)blockIdx.x * blockDim.x + threadIdx.x;
    if (i >= 2LL * N_EDGES) return;
    int is64 = g_is64;
    if (i < N_EDGES) {
        int d = ld_idx(eip, (long long)N_EDGES + i, is64);
        atomicAdd(&g_degp[d], 1);
    } else {
        long long e = i - N_EDGES;
        int d = ld_idx(ein, (long long)N_EDGES + e, is64);
        atomicAdd(&g_degn[d], 1);
    }
}

__global__ void k_dinv() {
    int i = blockIdx.x * blockDim.x + threadIdx.x;
    if (i < N_NODES) {
        g_dinvp[i] = rsqrtf((float)g_degp[i]);
        g_dinvn[i] = rsqrtf((float)g_degn[i]);
    }
}

__global__ void k_norm(const void* eip, const void* ein) {
    long long i = (long long)blockIdx.x * blockDim.x + threadIdx.x;
    if (i >= 2LL * N_EDGES) return;
    int is64 = g_is64;
    if (i < N_EDGES) {
        int s = ld_idx(eip, i, is64);
        int d = ld_idx(eip, (long long)N_EDGES + i, is64);
        g_normp[i] = g_dinvp[s] * g_dinvp[d];
    } else {
        long long e = i - N_EDGES;
        int s = ld_idx(ein, e, is64);
        int d = ld_idx(ein, (long long)N_EDGES + e, is64);
        g_normn[e] = g_dinvn[s] * g_dinvn[d];
    }
}

// ---------------- encoder: h = x @ W_enc^T + b_enc ----------------
__global__ void __launch_bounds__(256) k_encode(
    const float* __restrict__ x, const float* __restrict__ W_enc,
    const float* __restrict__ b_enc)
{
    __shared__ float Ws[N_FEAT * HID];   // transposed: Ws[k*HID + j] = W[j][k]
    __shared__ float xs[8][N_FEAT];
    int tid = threadIdx.x;
    for (int i = tid; i < N_FEAT * HID; i += 256) {
        int j = i & (HID - 1), k = i >> 6;
        Ws[i] = W_enc[j * N_FEAT + k];
    }
    __syncthreads();
    int lane = tid & 31, warp = tid >> 5;
    float b0 = b_enc[2 * lane], b1 = b_enc[2 * lane + 1];
    for (int row = blockIdx.x * 8 + warp; row < N_NODES; row += gridDim.x * 8) {
        float4 xv = ((const float4*)(x + (size_t)row * N_FEAT))[lane];
        ((float4*)xs[warp])[lane] = xv;
        __syncwarp();
        float a0 = b0, a1 = b1;
        #pragma unroll 32
        for (int k = 0; k < N_FEAT; k++) {
            float xk = xs[warp][k];
            float2 w = *(const float2*)&Ws[k * HID + 2 * lane];
            a0 += xk * w.x; a1 += xk * w.y;
        }
        float2 r = make_float2(a0, a1);
        ((float2*)(g_h + (size_t)row * HID))[lane] = r;
        ((float2*)(g_hin + (size_t)row * HID))[lane] = r;
        __syncwarp();
    }
}

// ---------------- LN + dual 64x64 GEMM + self-loop init ----------------
__global__ void __launch_bounds__(256) k_ln_gemm(
    const float* __restrict__ gamma, const float* __restrict__ beta,
    const float* __restrict__ W_pos, const float* __restrict__ W_neg)
{
    __shared__ float Wp[HID * HID], Wn[HID * HID];  // transposed
    __shared__ float hs[8][HID];
    int tid = threadIdx.x;
    for (int i = tid; i < HID * HID; i += 256) {
        int j = i & 63, k = i >> 6;
        Wp[i] = W_pos[j * HID + k];
        Wn[i] = W_neg[j * HID + k];
    }
    __syncthreads();
    int lane = tid & 31, warp = tid >> 5;
    float2 ga = *(const float2*)&gamma[2 * lane];
    float2 be = *(const float2*)&beta[2 * lane];
    for (int row = blockIdx.x * 8 + warp; row < N_NODES; row += gridDim.x * 8) {
        size_t off = (size_t)row * HID;
        float2 v = ((const float2*)(g_hin + off))[lane];
        float s = v.x + v.y;
        #pragma unroll
        for (int o = 16; o; o >>= 1) s += __shfl_xor_sync(0xffffffffu, s, o);
        float mu = s * (1.0f / HID);
        float dx = v.x - mu, dy = v.y - mu;
        float q = dx * dx + dy * dy;
        #pragma unroll
        for (int o = 16; o; o >>= 1) q += __shfl_xor_sync(0xffffffffu, q, o);
        float rs = rsqrtf(q * (1.0f / HID) + LN_EPS);
        hs[warp][2 * lane]     = dx * rs * ga.x + be.x;
        hs[warp][2 * lane + 1] = dy * rs * ga.y + be.y;
        __syncwarp();
        float p0 = 0.f, p1 = 0.f, n0 = 0.f, n1 = 0.f;
        #pragma unroll
        for (int k = 0; k < HID; k++) {
            float hk = hs[warp][k];
            float2 wp = *(const float2*)&Wp[k * HID + 2 * lane];
            float2 wn = *(const float2*)&Wn[k * HID + 2 * lane];
            p0 += hk * wp.x; p1 += hk * wp.y;
            n0 += hk * wn.x; n1 += hk * wn.y;
        }
        ((float2*)(g_xp + off))[lane] = make_float2(p0, p1);
        ((float2*)(g_xn + off))[lane] = make_float2(n0, n1);
        float dp = g_dinvp[row]; float d2p = dp * dp;
        float dn = g_dinvn[row]; float d2n = dn * dn;
        ((float2*)(g_aggp + off))[lane] = make_float2(d2p * p0, d2p * p1);
        ((float2*)(g_aggn + off))[lane] = make_float2(d2n * n0, d2n * n1);
        __syncwarp();
    }
}

// ---------------- edge scatter: 16 lanes per edge, red.v4 ----------------
__global__ void __launch_bounds__(256) k_scatter(const void* __restrict__ eip,
                                                 const void* __restrict__ ein)
{
    long long t  = (long long)blockIdx.x * blockDim.x + threadIdx.x;
    long long eg = t >> 4;
    int l = (int)(t & 15);
    if (eg >= 2LL * N_EDGES) return;
    int is64 = g_is64;
    const void* ep; const float* xsrc; float* agg; const float* nrm;
    long long e;
    if (eg < N_EDGES) { ep = eip; xsrc = g_xp; agg = g_aggp; nrm = g_normp; e = eg; }
    else              { ep = ein; xsrc = g_xn; agg = g_aggn; nrm = g_normn; e = eg - N_EDGES; }
    int s = ld_idx(ep, e, is64);
    int d = ld_idx(ep, (long long)N_EDGES + e, is64);
    float w = nrm[e];
    float4 v = ((const float4*)(xsrc + (size_t)s * HID))[l];
    float4 m = make_float4(v.x * w, v.y * w, v.z * w, v.w * w);
    float* a = agg + (size_t)d * HID + l * 4;
    asm volatile("red.global.add.v4.f32 [%0], {%1,%2,%3,%4};"
                 :: "l"(a), "f"(m.x), "f"(m.y), "f"(m.z), "f"(m.w) : "memory");
}

// ---------------- psi GEMMs + clip + RK4 stage update ----------------
__global__ void __launch_bounds__(256) k_delta_rk4(
    const float* __restrict__ b_pos, const float* __restrict__ b_neg,
    const float* __restrict__ Wpp,   const float* __restrict__ Wpn,
    const float* __restrict__ bpp,   const float* __restrict__ bpn,
    const float* __restrict__ t, int stage, float* __restrict__ dout)
{
    __shared__ float Wp[HID * HID], Wn[HID * HID];  // transposed
    __shared__ float as_[8][HID], ns_[8][HID];
    int tid = threadIdx.x;
    for (int i = tid; i < HID * HID; i += 256) {
        int j = i & 63, k = i >> 6;
        Wp[i] = Wpp[j * HID + k];
        Wn[i] = Wpn[j * HID + k];
    }
    __syncthreads();
    int lane = tid & 31, warp = tid >> 5;
    float dt = (t[1] - t[0]) * 0.5f;   // /RK4_STEPS
    float2 bp = *(const float2*)&b_pos[2 * lane];
    float2 bn = *(const float2*)&b_neg[2 * lane];
    float bs0 = bpp[2 * lane] + bpn[2 * lane];
    float bs1 = bpp[2 * lane + 1] + bpn[2 * lane + 1];
    for (int row = blockIdx.x * 8 + warp; row < N_NODES; row += gridDim.x * 8) {
        size_t off = (size_t)row * HID;
        float2 ap = ((const float2*)(g_aggp + off))[lane];
        float2 an = ((const float2*)(g_aggn + off))[lane];
        as_[warp][2 * lane]     = ap.x + bp.x;
        as_[warp][2 * lane + 1] = ap.y + bp.y;
        ns_[warp][2 * lane]     = an.x + bn.x;
        ns_[warp][2 * lane + 1] = an.y + bn.y;
        __syncwarp();
        float a0 = bs0, a1 = bs1;
        #pragma unroll
        for (int k = 0; k < HID; k++) {
            float akp = as_[warp][k], akn = ns_[warp][k];
            float2 wp = *(const float2*)&Wp[k * HID + 2 * lane];
            float2 wn = *(const float2*)&Wn[k * HID + 2 * lane];
            a0 += akp * wp.x + akn * wn.x;
            a1 += akp * wp.y + akn * wn.y;
        }
        a0 = fminf(fmaxf(a0, -50.f), 50.f);
        a1 = fminf(fmaxf(a1, -50.f), 50.f);
        float2 h = ((const float2*)(g_h + off))[lane];
        if (stage == 0) {
            ((float2*)(g_kacc + off))[lane] = make_float2(a0, a1);
            ((float2*)(g_hin + off))[lane] =
                make_float2(h.x + 0.5f * dt * a0, h.y + 0.5f * dt * a1);
        } else if (stage == 1) {
            float2 kv = ((float2*)(g_kacc + off))[lane];
            kv.x += 2.f * a0; kv.y += 2.f * a1;
            ((float2*)(g_kacc + off))[lane] = kv;
            ((float2*)(g_hin + off))[lane] =
                make_float2(h.x + 0.5f * dt * a0, h.y + 0.5f * dt * a1);
        } else if (stage == 2) {
            float2 kv = ((float2*)(g_kacc + off))[lane];
            kv.x += 2.f * a0; kv.y += 2.f * a1;
            ((float2*)(g_kacc + off))[lane] = kv;
            ((float2*)(g_hin + off))[lane] =
                make_float2(h.x + dt * a0, h.y + dt * a1);
        } else {
            float2 kv = ((float2*)(g_kacc + off))[lane];
            float c = dt * (1.0f / 6.0f);
            float2 hn2 = make_float2(h.x + c * (kv.x + a0), h.y + c * (kv.y + a1));
            ((float2*)(g_h + off))[lane]   = hn2;
            ((float2*)(g_hin + off))[lane] = hn2;
            if (dout) ((float2*)(dout + off))[lane] = hn2;
        }
        __syncwarp();
    }
}

// ---------------- launch ----------------
extern "C" void kernel_launch(void* const* d_in, const int* in_sizes, int n_in,
                              void* d_out, int out_size)
{
    const float* x     = (const float*)d_in[0];
    const void*  eip   = d_in[1];
    const void*  ein   = d_in[2];
    const float* t     = (const float*)d_in[3];
    const float* W_enc = (const float*)d_in[4];
    const float* b_enc = (const float*)d_in[5];
    const float* W_pos = (const float*)d_in[6];
    const float* b_pos = (const float*)d_in[7];
    const float* W_neg = (const float*)d_in[8];
    const float* b_neg = (const float*)d_in[9];
    const float* Wpp   = (const float*)d_in[10];
    const float* bpp   = (const float*)d_in[11];
    const float* Wpn   = (const float*)d_in[12];
    const float* bpn   = (const float*)d_in[13];
    const float* gamma = (const float*)d_in[14];
    const float* beta  = (const float*)d_in[15];
    float* dout = (float*)d_out;

    const int nb_nodes = (N_NODES + 255) / 256;
    const int nb_edges = (int)((2LL * N_EDGES + 255) / 256);
    const int nb_rows  = (N_NODES + 7) / 8;                      // warp per row
    const unsigned nb_scat = (unsigned)((2LL * N_EDGES * 16 + 255) / 256);

    k_detect<<<1, 1>>>(eip);
    k_initdeg<<<nb_nodes, 256>>>();
    k_count<<<nb_edges, 256>>>(eip, ein);
    k_dinv<<<nb_nodes, 256>>>();
    k_norm<<<nb_edges, 256>>>(eip, ein);
    k_encode<<<nb_rows, 256>>>(x, W_enc, b_enc);

    for (int step = 0; step < 2; step++) {
        for (int stage = 0; stage < 4; stage++) {
            k_ln_gemm<<<nb_rows, 256>>>(gamma, beta, W_pos, W_neg);
            k_scatter<<<nb_scat, 256>>>(eip, ein);
            bool last = (step == 1 && stage == 3);
            k_delta_rk4<<<nb_rows, 256>>>(b_pos, b_neg, Wpp, Wpn, bpp, bpn,
                                          t, stage, last ? dout : nullptr);
        }
    }
}

// round 6
// speedup vs baseline: 2.8583x; 2.8583x over previous
#include <cuda_runtime.h>
#include <cstdint>

#define N_NODES 50000
#define N_FEAT  128
#define HID     64
#define N_EDGES 1600000
#define LN_EPS  1e-5f

// ---------------- scratch (device globals; no allocation) ----------------
__device__ float g_h   [N_NODES * HID];   // RK4 state at step start
__device__ float g_kacc[N_NODES * HID];   // RK4 accumulator
__device__ float g_xp  [N_NODES * HID];   // hn @ W_pos^T
__device__ float g_xn  [N_NODES * HID];   // hn @ W_neg^T
__device__ float g_aggp[N_NODES * HID];   // pos aggregation
__device__ float g_aggn[N_NODES * HID];   // neg aggregation
__device__ int   g_degp[N_NODES];
__device__ int   g_degn[N_NODES];
__device__ float g_dinvp[N_NODES];
__device__ float g_dinvn[N_NODES];
// CSR (sorted by dst)
__device__ int   g_offp[N_NODES + 1];
__device__ int   g_offn[N_NODES + 1];
__device__ int   g_curp[N_NODES];
__device__ int   g_curn[N_NODES];
__device__ int   g_srcp[N_EDGES];
__device__ int   g_srcn[N_EDGES];
__device__ float g_nrmp[N_EDGES];
__device__ float g_nrmn[N_EDGES];
__device__ int   g_is64;

// ---------------- helpers ----------------
__device__ __forceinline__ int ld_idx(const void* p, long long i, int is64) {
    if (is64) return (int)((const long long*)p)[i];
    return ((const int*)p)[i];
}

__global__ void k_detect(const void* eip) {
    const int* w = (const int*)eip;
    int ok = 1;
    for (int i = 0; i < 32; i++)
        if (w[2 * i + 1] != 0) ok = 0;
    g_is64 = ok;
}

__global__ void k_initdeg() {
    int i = blockIdx.x * blockDim.x + threadIdx.x;
    if (i < N_NODES) { g_degp[i] = 1; g_degn[i] = 1; }
}

__global__ void k_count(const void* eip, const void* ein) {
    long long i = (long long)blockIdx.x * blockDim.x + threadIdx.x;
    if (i >= 2LL * N_EDGES) return;
    int is64 = g_is64;
    if (i < N_EDGES) {
        int d = ld_idx(eip, (long long)N_EDGES + i, is64);
        atomicAdd(&g_degp[d], 1);
    } else {
        long long e = i - N_EDGES;
        int d = ld_idx(ein, (long long)N_EDGES + e, is64);
        atomicAdd(&g_degn[d], 1);
    }
}

__global__ void k_dinv() {
    int i = blockIdx.x * blockDim.x + threadIdx.x;
    if (i < N_NODES) {
        g_dinvp[i] = rsqrtf((float)g_degp[i]);
        g_dinvn[i] = rsqrtf((float)g_degn[i]);
    }
}

// exclusive scan of (deg-1) for both edge sets; writes offsets + cursors
__global__ void __launch_bounds__(1024) k_scan() {
    __shared__ int swp[32], swn[32];
    __shared__ int totp, totn;
    int tid = threadIdx.x, lane = tid & 31, warp = tid >> 5;
    int carryP = 0, carryN = 0;
    for (int base = 0; base < N_NODES; base += 1024) {
        int i = base + tid;
        int cp = (i < N_NODES) ? g_degp[i] - 1 : 0;
        int cn = (i < N_NODES) ? g_degn[i] - 1 : 0;
        int sp = cp, sn = cn;
        #pragma unroll
        for (int o = 1; o < 32; o <<= 1) {
            int vp = __shfl_up_sync(0xffffffffu, sp, o);
            int vn = __shfl_up_sync(0xffffffffu, sn, o);
            if (lane >= o) { sp += vp; sn += vn; }
        }
        if (lane == 31) { swp[warp] = sp; swn[warp] = sn; }
        __syncthreads();
        if (warp == 0) {
            int op = swp[lane], on = swn[lane];
            int wp = op, wn = on;
            #pragma unroll
            for (int o = 1; o < 32; o <<= 1) {
                int vp = __shfl_up_sync(0xffffffffu, wp, o);
                int vn = __shfl_up_sync(0xffffffffu, wn, o);
                if (lane >= o) { wp += vp; wn += vn; }
            }
            swp[lane] = wp - op;   // exclusive warp offsets
            swn[lane] = wn - on;
            if (lane == 31) { totp = wp; totn = wn; }
        }
        __syncthreads();
        if (i < N_NODES) {
            int exP = carryP + swp[warp] + (sp - cp);
            int exN = carryN + swn[warp] + (sn - cn);
            g_offp[i] = exP; g_curp[i] = exP;
            g_offn[i] = exN; g_curn[i] = exN;
        }
        carryP += totp; carryN += totn;
        __syncthreads();
    }
    if (tid == 0) { g_offp[N_NODES] = carryP; g_offn[N_NODES] = carryN; }
}

// reorder edges into CSR-by-dst, storing src + precomputed norm
__global__ void k_reorder(const void* eip, const void* ein) {
    long long i = (long long)blockIdx.x * blockDim.x + threadIdx.x;
    if (i >= 2LL * N_EDGES) return;
    int is64 = g_is64;
    if (i < N_EDGES) {
        int s = ld_idx(eip, i, is64);
        int d = ld_idx(eip, (long long)N_EDGES + i, is64);
        int p = atomicAdd(&g_curp[d], 1);
        g_srcp[p] = s;
        g_nrmp[p] = g_dinvp[s] * g_dinvp[d];
    } else {
        long long e = i - N_EDGES;
        int s = ld_idx(ein, e, is64);
        int d = ld_idx(ein, (long long)N_EDGES + e, is64);
        int p = atomicAdd(&g_curn[d], 1);
        g_srcn[p] = s;
        g_nrmn[p] = g_dinvn[s] * g_dinvn[d];
    }
}

// ---------------- encoder: h = x @ W_enc^T + b_enc ----------------
__global__ void __launch_bounds__(256) k_encode(
    const float* __restrict__ x, const float* __restrict__ W_enc,
    const float* __restrict__ b_enc)
{
    __shared__ float Ws[N_FEAT * HID];   // transposed: Ws[k*HID + j] = W[j][k]
    __shared__ float xs[8][N_FEAT];
    int tid = threadIdx.x;
    for (int i = tid; i < N_FEAT * HID; i += 256) {
        int j = i & (HID - 1), k = i >> 6;
        Ws[i] = W_enc[j * N_FEAT + k];
    }
    __syncthreads();
    int lane = tid & 31, warp = tid >> 5;
    float b0 = b_enc[2 * lane], b1 = b_enc[2 * lane + 1];
    for (int row = blockIdx.x * 8 + warp; row < N_NODES; row += gridDim.x * 8) {
        float4 xv = ((const float4*)(x + (size_t)row * N_FEAT))[lane];
        ((float4*)xs[warp])[lane] = xv;
        __syncwarp();
        float a0 = b0, a1 = b1;
        #pragma unroll 32
        for (int k = 0; k < N_FEAT; k++) {
            float xk = xs[warp][k];
            float2 w = *(const float2*)&Ws[k * HID + 2 * lane];
            a0 += xk * w.x; a1 += xk * w.y;
        }
        ((float2*)(g_h + (size_t)row * HID))[lane] = make_float2(a0, a1);
        __syncwarp();
    }
}

// ---------------- prologue LN + dual 64x64 GCN GEMM (from g_h) ----------------
__global__ void __launch_bounds__(256) k_ln0(
    const float* __restrict__ gamma, const float* __restrict__ beta,
    const float* __restrict__ W_pos, const float* __restrict__ W_neg)
{
    __shared__ float Wp[HID * HID], Wn[HID * HID];  // transposed
    __shared__ float hs[8][HID];
    int tid = threadIdx.x;
    for (int i = tid; i < HID * HID; i += 256) {
        int j = i & 63, k = i >> 6;
        Wp[i] = W_pos[j * HID + k];
        Wn[i] = W_neg[j * HID + k];
    }
    __syncthreads();
    int lane = tid & 31, warp = tid >> 5;
    float2 ga = *(const float2*)&gamma[2 * lane];
    float2 be = *(const float2*)&beta[2 * lane];
    for (int row = blockIdx.x * 8 + warp; row < N_NODES; row += gridDim.x * 8) {
        size_t off = (size_t)row * 32;
        float2 v = ((const float2*)g_h)[off + lane];
        float s = v.x + v.y;
        #pragma unroll
        for (int o = 16; o; o >>= 1) s += __shfl_xor_sync(0xffffffffu, s, o);
        float mu = s * (1.0f / HID);
        float dx = v.x - mu, dy = v.y - mu;
        float q = dx * dx + dy * dy;
        #pragma unroll
        for (int o = 16; o; o >>= 1) q += __shfl_xor_sync(0xffffffffu, q, o);
        float rs = rsqrtf(q * (1.0f / HID) + LN_EPS);
        hs[warp][2 * lane]     = dx * rs * ga.x + be.x;
        hs[warp][2 * lane + 1] = dy * rs * ga.y + be.y;
        __syncwarp();
        float p0 = 0.f, p1 = 0.f, n0 = 0.f, n1 = 0.f;
        #pragma unroll
        for (int k = 0; k < HID; k++) {
            float hk = hs[warp][k];
            float2 wp = *(const float2*)&Wp[k * HID + 2 * lane];
            float2 wn = *(const float2*)&Wn[k * HID + 2 * lane];
            p0 += hk * wp.x; p1 += hk * wp.y;
            n0 += hk * wn.x; n1 += hk * wn.y;
        }
        ((float2*)g_xp)[off + lane] = make_float2(p0, p1);
        ((float2*)g_xn)[off + lane] = make_float2(n0, n1);
        __syncwarp();
    }
}

// ---------------- CSR gather: 1 warp per dst node, register accumulation ----------------
__global__ void __launch_bounds__(256) k_gather() {
    int gw = blockIdx.x * 8 + (threadIdx.x >> 5);
    int lane = threadIdx.x & 31;
    const int* off; const int* srcv; const float* nrm;
    const float2* xv; float* agg; const float* dinv;
    int n;
    if (gw < N_NODES) {
        n = gw; off = g_offp; srcv = g_srcp; nrm = g_nrmp;
        xv = (const float2*)g_xp; agg = g_aggp; dinv = g_dinvp;
    } else {
        n = gw - N_NODES; off = g_offn; srcv = g_srcn; nrm = g_nrmn;
        xv = (const float2*)g_xn; agg = g_aggn; dinv = g_dinvn;
    }
    float di = dinv[n];
    float ws = di * di;                        // self-loop norm
    float2 acc = xv[(size_t)n * 32 + lane];
    acc.x *= ws; acc.y *= ws;
    int b = off[n], e = off[n + 1];
    int i = b;
    for (; i + 4 <= e; i += 4) {
        int s0 = srcv[i], s1 = srcv[i + 1], s2 = srcv[i + 2], s3 = srcv[i + 3];
        float w0 = nrm[i], w1 = nrm[i + 1], w2 = nrm[i + 2], w3 = nrm[i + 3];
        float2 v0 = xv[(size_t)s0 * 32 + lane];
        float2 v1 = xv[(size_t)s1 * 32 + lane];
        float2 v2 = xv[(size_t)s2 * 32 + lane];
        float2 v3 = xv[(size_t)s3 * 32 + lane];
        acc.x += w0 * v0.x + w1 * v1.x + w2 * v2.x + w3 * v3.x;
        acc.y += w0 * v0.y + w1 * v1.y + w2 * v2.y + w3 * v3.y;
    }
    for (; i < e; i++) {
        int s = srcv[i]; float w = nrm[i];
        float2 v = xv[(size_t)s * 32 + lane];
        acc.x += w * v.x; acc.y += w * v.y;
    }
    ((float2*)agg)[(size_t)n * 32 + lane] = acc;
}

// ---------------- fused: psi GEMMs + clip + RK4 update + LN + GCN GEMMs ----------------
// dynamic smem: Wp,Wn (psi^T) + Gp,Gn (gcn^T) = 64KB, + as_,ns_,hs = 6KB
#define SM_STAGE_BYTES ((4 * HID * HID + 3 * 8 * HID) * 4)

__global__ void __launch_bounds__(256) k_stage(
    const float* __restrict__ b_pos, const float* __restrict__ b_neg,
    const float* __restrict__ Wpp_g, const float* __restrict__ bpp,
    const float* __restrict__ Wpn_g, const float* __restrict__ bpn,
    const float* __restrict__ gamma, const float* __restrict__ beta,
    const float* __restrict__ Wposg, const float* __restrict__ Wnegg,
    const float* __restrict__ t, int stage, int last, float* __restrict__ dout)
{
    extern __shared__ float sm[];
    float* Wp = sm;
    float* Wn = sm + HID * HID;
    float* Gp = sm + 2 * HID * HID;
    float* Gn = sm + 3 * HID * HID;
    float* as_ = sm + 4 * HID * HID;     // [8][HID]
    float* ns_ = as_ + 8 * HID;
    float* hs  = ns_ + 8 * HID;

    int tid = threadIdx.x;
    for (int i = tid; i < HID * HID; i += 256) {
        int j = i & 63, k = i >> 6;
        Wp[i] = Wpp_g[j * HID + k];
        Wn[i] = Wpn_g[j * HID + k];
        Gp[i] = Wposg[j * HID + k];
        Gn[i] = Wnegg[j * HID + k];
    }
    __syncthreads();

    int lane = tid & 31, warp = tid >> 5;
    float dt = (t[1] - t[0]) * 0.5f;     // / RK4_STEPS
    float2 bp = *(const float2*)&b_pos[2 * lane];
    float2 bn = *(const float2*)&b_neg[2 * lane];
    float bs0 = bpp[2 * lane] + bpn[2 * lane];
    float bs1 = bpp[2 * lane + 1] + bpn[2 * lane + 1];
    float2 ga = *(const float2*)&gamma[2 * lane];
    float2 be = *(const float2*)&beta[2 * lane];
    float* aw = as_ + warp * HID;
    float* nw = ns_ + warp * HID;
    float* hw = hs + warp * HID;
    bool final3 = (stage == 3) && last;

    for (int row = blockIdx.x * 8 + warp; row < N_NODES; row += gridDim.x * 8) {
        size_t off = (size_t)row * 32;
        float2 ap = ((const float2*)g_aggp)[off + lane];
        float2 an = ((const float2*)g_aggn)[off + lane];
        aw[2 * lane]     = ap.x + bp.x;
        aw[2 * lane + 1] = ap.y + bp.y;
        nw[2 * lane]     = an.x + bn.x;
        nw[2 * lane + 1] = an.y + bn.y;
        __syncwarp();
        float a0 = bs0, a1 = bs1;
        #pragma unroll
        for (int k = 0; k < HID; k++) {
            float akp = aw[k], akn = nw[k];
            float2 wp = *(const float2*)&Wp[k * HID + 2 * lane];
            float2 wn = *(const float2*)&Wn[k * HID + 2 * lane];
            a0 += akp * wp.x + akn * wn.x;
            a1 += akp * wp.y + akn * wn.y;
        }
        a0 = fminf(fmaxf(a0, -50.f), 50.f);
        a1 = fminf(fmaxf(a1, -50.f), 50.f);

        float2 h = ((const float2*)g_h)[off + lane];
        float hx, hy;
        if (stage == 0) {
            ((float2*)g_kacc)[off + lane] = make_float2(a0, a1);
            hx = h.x + 0.5f * dt * a0; hy = h.y + 0.5f * dt * a1;
        } else if (stage == 1) {
            float2 kv = ((float2*)g_kacc)[off + lane];
            kv.x += 2.f * a0; kv.y += 2.f * a1;
            ((float2*)g_kacc)[off + lane] = kv;
            hx = h.x + 0.5f * dt * a0; hy = h.y + 0.5f * dt * a1;
        } else if (stage == 2) {
            float2 kv = ((float2*)g_kacc)[off + lane];
            kv.x += 2.f * a0; kv.y += 2.f * a1;
            ((float2*)g_kacc)[off + lane] = kv;
            hx = h.x + dt * a0; hy = h.y + dt * a1;
        } else {
            float2 kv = ((float2*)g_kacc)[off + lane];
            float c = dt * (1.0f / 6.0f);
            hx = h.x + c * (kv.x + a0);
            hy = h.y + c * (kv.y + a1);
            ((float2*)g_h)[off + lane] = make_float2(hx, hy);
            if (last) ((float2*)dout)[off + lane] = make_float2(hx, hy);
        }

        if (!final3) {
            // LN(hx,hy) + dual GCN GEMM -> xp, xn
            float s = hx + hy;
            #pragma unroll
            for (int o = 16; o; o >>= 1) s += __shfl_xor_sync(0xffffffffu, s, o);
            float mu = s * (1.0f / HID);
            float dx = hx - mu, dy = hy - mu;
            float q = dx * dx + dy * dy;
            #pragma unroll
            for (int o = 16; o; o >>= 1) q += __shfl_xor_sync(0xffffffffu, q, o);
            float rs = rsqrtf(q * (1.0f / HID) + LN_EPS);
            hw[2 * lane]     = dx * rs * ga.x + be.x;
            hw[2 * lane + 1] = dy * rs * ga.y + be.y;
            __syncwarp();
            float p0 = 0.f, p1 = 0.f, n0 = 0.f, n1 = 0.f;
            #pragma unroll
            for (int k = 0; k < HID; k++) {
                float hk = hw[k];
                float2 wp = *(const float2*)&Gp[k * HID + 2 * lane];
                float2 wn = *(const float2*)&Gn[k * HID + 2 * lane];
                p0 += hk * wp.x; p1 += hk * wp.y;
                n0 += hk * wn.x; n1 += hk * wn.y;
            }
            ((float2*)g_xp)[off + lane] = make_float2(p0, p1);
            ((float2*)g_xn)[off + lane] = make_float2(n0, n1);
        }
        __syncwarp();
    }
}

// ---------------- launch ----------------
extern "C" void kernel_launch(void* const* d_in, const int* in_sizes, int n_in,
                              void* d_out, int out_size)
{
    const float* x     = (const float*)d_in[0];
    const void*  eip   = d_in[1];
    const void*  ein   = d_in[2];
    const float* t     = (const float*)d_in[3];
    const float* W_enc = (const float*)d_in[4];
    const float* b_enc = (const float*)d_in[5];
    const float* W_pos = (const float*)d_in[6];
    const float* b_pos = (const float*)d_in[7];
    const float* W_neg = (const float*)d_in[8];
    const float* b_neg = (const float*)d_in[9];
    const float* Wpp   = (const float*)d_in[10];
    const float* bpp   = (const float*)d_in[11];
    const float* Wpn   = (const float*)d_in[12];
    const float* bpn   = (const float*)d_in[13];
    const float* gamma = (const float*)d_in[14];
    const float* beta  = (const float*)d_in[15];
    float* dout = (float*)d_out;

    cudaFuncSetAttribute(k_stage, cudaFuncAttributeMaxDynamicSharedMemorySize,
                         SM_STAGE_BYTES);

    const int nb_nodes  = (N_NODES + 255) / 256;
    const int nb_edges  = (int)((2LL * N_EDGES + 255) / 256);
    const int nb_gather = (2 * N_NODES + 7) / 8;   // 1 warp per (node, set)
    const int nb_gs     = 888;                     // grid-stride row kernels

    k_detect<<<1, 1>>>(eip);
    k_initdeg<<<nb_nodes, 256>>>();
    k_count<<<nb_edges, 256>>>(eip, ein);
    k_dinv<<<nb_nodes, 256>>>();
    k_scan<<<1, 1024>>>();
    k_reorder<<<nb_edges, 256>>>(eip, ein);
    k_encode<<<nb_gs, 256>>>(x, W_enc, b_enc);
    k_ln0<<<nb_gs, 256>>>(gamma, beta, W_pos, W_neg);

    for (int it = 0; it < 8; it++) {
        k_gather<<<nb_gather, 256>>>();
        int stage = it & 3;
        int last  = (it == 7) ? 1 : 0;
        k_stage<<<444, 256, SM_STAGE_BYTES>>>(
            b_pos, b_neg, Wpp, bpp, Wpn, bpn, gamma, beta,
            W_pos, W_neg, t, stage, last, dout);
    }
}

// round 8
// speedup vs baseline: 2.8829x; 1.0086x over previous
#include <cuda_runtime.h>
#include <cuda_fp16.h>
#include <cstdint>

#define N_NODES 50000
#define N_FEAT  128
#define HID     64
#define N_EDGES 1600000
#define LN_EPS  1e-5f

// ---------------- scratch (device globals; no allocation) ----------------
__device__ float  g_h   [N_NODES * HID];   // RK4 state at step start
__device__ float  g_kacc[N_NODES * HID];   // RK4 accumulator
__device__ __half g_xp  [N_NODES * HID];   // hn @ W_pos^T (fp16 messages)
__device__ __half g_xn  [N_NODES * HID];   // hn @ W_neg^T
__device__ float  g_aggp[N_NODES * HID];   // pos aggregation (fp32)
__device__ float  g_aggn[N_NODES * HID];   // neg aggregation
__device__ int    g_degp[N_NODES];
__device__ int    g_degn[N_NODES];
__device__ float  g_dinvp[N_NODES];
__device__ float  g_dinvn[N_NODES];
// CSR (sorted by dst); edge payload packed: {src, norm-as-int}
__device__ int    g_offp[N_NODES + 1];
__device__ int    g_offn[N_NODES + 1];
__device__ int    g_curp[N_NODES];
__device__ int    g_curn[N_NODES];
__device__ int2   g_edgep[N_EDGES];
__device__ int2   g_edgen[N_EDGES];
__device__ int    g_is64;

// ---------------- helpers ----------------
__device__ __forceinline__ int ld_idx(const void* p, long long i, int is64) {
    if (is64) return (int)((const long long*)p)[i];
    return ((const int*)p)[i];
}

__global__ void k_detect(const void* eip) {
    const int* w = (const int*)eip;
    int ok = 1;
    for (int i = 0; i < 32; i++)
        if (w[2 * i + 1] != 0) ok = 0;
    g_is64 = ok;
}

__global__ void k_initdeg() {
    int i = blockIdx.x * blockDim.x + threadIdx.x;
    if (i < N_NODES) { g_degp[i] = 1; g_degn[i] = 1; }
}

__global__ void k_count(const void* eip, const void* ein) {
    long long i = (long long)blockIdx.x * blockDim.x + threadIdx.x;
    if (i >= 2LL * N_EDGES) return;
    int is64 = g_is64;
    if (i < N_EDGES) {
        int d = ld_idx(eip, (long long)N_EDGES + i, is64);
        atomicAdd(&g_degp[d], 1);
    } else {
        long long e = i - N_EDGES;
        int d = ld_idx(ein, (long long)N_EDGES + e, is64);
        atomicAdd(&g_degn[d], 1);
    }
}

__global__ void k_dinv() {
    int i = blockIdx.x * blockDim.x + threadIdx.x;
    if (i < N_NODES) {
        g_dinvp[i] = rsqrtf((float)g_degp[i]);
        g_dinvn[i] = rsqrtf((float)g_degn[i]);
    }
}

// exclusive scan of (deg-1) for both edge sets; writes offsets + cursors
__global__ void __launch_bounds__(1024) k_scan() {
    __shared__ int swp[32], swn[32];
    __shared__ int totp, totn;
    int tid = threadIdx.x, lane = tid & 31, warp = tid >> 5;
    int carryP = 0, carryN = 0;
    for (int base = 0; base < N_NODES; base += 1024) {
        int i = base + tid;
        int cp = (i < N_NODES) ? g_degp[i] - 1 : 0;
        int cn = (i < N_NODES) ? g_degn[i] - 1 : 0;
        int sp = cp, sn = cn;
        #pragma unroll
        for (int o = 1; o < 32; o <<= 1) {
            int vp = __shfl_up_sync(0xffffffffu, sp, o);
            int vn = __shfl_up_sync(0xffffffffu, sn, o);
            if (lane >= o) { sp += vp; sn += vn; }
        }
        if (lane == 31) { swp[warp] = sp; swn[warp] = sn; }
        __syncthreads();
        if (warp == 0) {
            int op = swp[lane], on = swn[lane];
            int wp = op, wn = on;
            #pragma unroll
            for (int o = 1; o < 32; o <<= 1) {
                int vp = __shfl_up_sync(0xffffffffu, wp, o);
                int vn = __shfl_up_sync(0xffffffffu, wn, o);
                if (lane >= o) { wp += vp; wn += vn; }
            }
            swp[lane] = wp - op;   // exclusive warp offsets
            swn[lane] = wn - on;
            if (lane == 31) { totp = wp; totn = wn; }
        }
        __syncthreads();
        if (i < N_NODES) {
            int exP = carryP + swp[warp] + (sp - cp);
            int exN = carryN + swn[warp] + (sn - cn);
            g_offp[i] = exP; g_curp[i] = exP;
            g_offn[i] = exN; g_curn[i] = exN;
        }
        carryP += totp; carryN += totn;
        __syncthreads();
    }
    if (tid == 0) { g_offp[N_NODES] = carryP; g_offn[N_NODES] = carryN; }
}

// reorder edges into CSR-by-dst, one packed int2 {src, norm} per edge
__global__ void k_reorder(const void* eip, const void* ein) {
    long long i = (long long)blockIdx.x * blockDim.x + threadIdx.x;
    if (i >= 2LL * N_EDGES) return;
    int is64 = g_is64;
    if (i < N_EDGES) {
        int s = ld_idx(eip, i, is64);
        int d = ld_idx(eip, (long long)N_EDGES + i, is64);
        int p = atomicAdd(&g_curp[d], 1);
        float nrm = g_dinvp[s] * g_dinvp[d];
        g_edgep[p] = make_int2(s, __float_as_int(nrm));
    } else {
        long long e = i - N_EDGES;
        int s = ld_idx(ein, e, is64);
        int d = ld_idx(ein, (long long)N_EDGES + e, is64);
        int p = atomicAdd(&g_curn[d], 1);
        float nrm = g_dinvn[s] * g_dinvn[d];
        g_edgen[p] = make_int2(s, __float_as_int(nrm));
    }
}

// ---------------- encoder: h = x @ W_enc^T + b_enc ----------------
__global__ void __launch_bounds__(256) k_encode(
    const float* __restrict__ x, const float* __restrict__ W_enc,
    const float* __restrict__ b_enc)
{
    __shared__ float Ws[N_FEAT * HID];   // transposed: Ws[k*HID + j] = W[j][k]
    __shared__ float xs[8][N_FEAT];
    int tid = threadIdx.x;
    for (int i = tid; i < N_FEAT * HID; i += 256) {
        int j = i & (HID - 1), k = i >> 6;
        Ws[i] = W_enc[j * N_FEAT + k];
    }
    __syncthreads();
    int lane = tid & 31, warp = tid >> 5;
    float b0 = b_enc[2 * lane], b1 = b_enc[2 * lane + 1];
    for (int row = blockIdx.x * 8 + warp; row < N_NODES; row += gridDim.x * 8) {
        float4 xv = ((const float4*)(x + (size_t)row * N_FEAT))[lane];
        ((float4*)xs[warp])[lane] = xv;
        __syncwarp();
        float a0 = b0, a1 = b1;
        #pragma unroll 32
        for (int k = 0; k < N_FEAT; k++) {
            float xk = xs[warp][k];
            float2 w = *(const float2*)&Ws[k * HID + 2 * lane];
            a0 += xk * w.x; a1 += xk * w.y;
        }
        ((float2*)(g_h + (size_t)row * HID))[lane] = make_float2(a0, a1);
        __syncwarp();
    }
}

// ---------------- prologue LN + dual 64x64 GCN GEMM (from g_h) ----------------
__global__ void __launch_bounds__(256) k_ln0(
    const float* __restrict__ gamma, const float* __restrict__ beta,
    const float* __restrict__ W_pos, const float* __restrict__ W_neg)
{
    __shared__ float Wp[HID * HID], Wn[HID * HID];  // transposed
    __shared__ float hs[8][HID];
    int tid = threadIdx.x;
    for (int i = tid; i < HID * HID; i += 256) {
        int j = i & 63, k = i >> 6;
        Wp[i] = W_pos[j * HID + k];
        Wn[i] = W_neg[j * HID + k];
    }
    __syncthreads();
    int lane = tid & 31, warp = tid >> 5;
    float2 ga = *(const float2*)&gamma[2 * lane];
    float2 be = *(const float2*)&beta[2 * lane];
    for (int row = blockIdx.x * 8 + warp; row < N_NODES; row += gridDim.x * 8) {
        size_t off = (size_t)row * 32;
        float2 v = ((const float2*)g_h)[off + lane];
        float s = v.x + v.y;
        #pragma unroll
        for (int o = 16; o; o >>= 1) s += __shfl_xor_sync(0xffffffffu, s, o);
        float mu = s * (1.0f / HID);
        float dx = v.x - mu, dy = v.y - mu;
        float q = dx * dx + dy * dy;
        #pragma unroll
        for (int o = 16; o; o >>= 1) q += __shfl_xor_sync(0xffffffffu, q, o);
        float rs = rsqrtf(q * (1.0f / HID) + LN_EPS);
        hs[warp][2 * lane]     = dx * rs * ga.x + be.x;
        hs[warp][2 * lane + 1] = dy * rs * ga.y + be.y;
        __syncwarp();
        float p0 = 0.f, p1 = 0.f, n0 = 0.f, n1 = 0.f;
        #pragma unroll
        for (int k = 0; k < HID; k++) {
            float hk = hs[warp][k];
            float2 wp = *(const float2*)&Wp[k * HID + 2 * lane];
            float2 wn = *(const float2*)&Wn[k * HID + 2 * lane];
            p0 += hk * wp.x; p1 += hk * wp.y;
            n0 += hk * wn.x; n1 += hk * wn.y;
        }
        ((half2*)g_xp)[off + lane] = __floats2half2_rn(p0, p1);
        ((half2*)g_xn)[off + lane] = __floats2half2_rn(n0, n1);
        __syncwarp();
    }
}

// ---------------- CSR gather: 1 warp per dst node, fp16 rows, fp32 accum ----------------
__global__ void __launch_bounds__(256) k_gather() {
    int gw = blockIdx.x * 8 + (threadIdx.x >> 5);
    int lane = threadIdx.x & 31;
    const int* off; const int2* edg;
    const half2* xv; float* agg; const float* dinv;
    int n;
    if (gw < N_NODES) {
        n = gw; off = g_offp; edg = g_edgep;
        xv = (const half2*)g_xp; agg = g_aggp; dinv = g_dinvp;
    } else {
        n = gw - N_NODES; off = g_offn; edg = g_edgen;
        xv = (const half2*)g_xn; agg = g_aggn; dinv = g_dinvn;
    }
    float di = dinv[n];
    float ws = di * di;                        // self-loop norm
    float2 self = __half22float2(xv[(size_t)n * 32 + lane]);
    float2 acc0 = make_float2(self.x * ws, self.y * ws);
    float2 acc1 = make_float2(0.f, 0.f);
    int b = off[n], e = off[n + 1];
    int i = b;
    for (; i + 4 <= e; i += 4) {
        int2 e0 = edg[i],     e1 = edg[i + 1];
        int2 e2 = edg[i + 2], e3 = edg[i + 3];
        float2 v0 = __half22float2(xv[(size_t)e0.x * 32 + lane]);
        float2 v1 = __half22float2(xv[(size_t)e1.x * 32 + lane]);
        float2 v2 = __half22float2(xv[(size_t)e2.x * 32 + lane]);
        float2 v3 = __half22float2(xv[(size_t)e3.x * 32 + lane]);
        float w0 = __int_as_float(e0.y), w1 = __int_as_float(e1.y);
        float w2 = __int_as_float(e2.y), w3 = __int_as_float(e3.y);
        acc0.x += w0 * v0.x + w2 * v2.x;
        acc0.y += w0 * v0.y + w2 * v2.y;
        acc1.x += w1 * v1.x + w3 * v3.x;
        acc1.y += w1 * v1.y + w3 * v3.y;
    }
    for (; i < e; i++) {
        int2 ed = edg[i];
        float w = __int_as_float(ed.y);
        float2 v = __half22float2(xv[(size_t)ed.x * 32 + lane]);
        acc0.x += w * v.x; acc0.y += w * v.y;
    }
    acc0.x += acc1.x; acc0.y += acc1.y;
    ((float2*)agg)[(size_t)n * 32 + lane] = acc0;
}

// ---------------- fused: psi GEMMs + clip + RK4 update + LN + GCN GEMMs ----------------
#define SM_STAGE_BYTES ((4 * HID * HID + 3 * 8 * HID) * 4)

__global__ void __launch_bounds__(256) k_stage(
    const float* __restrict__ b_pos, const float* __restrict__ b_neg,
    const float* __restrict__ Wpp_g, const float* __restrict__ bpp,
    const float* __restrict__ Wpn_g, const float* __restrict__ bpn,
    const float* __restrict__ gamma, const float* __restrict__ beta,
    const float* __restrict__ Wposg, const float* __restrict__ Wnegg,
    const float* __restrict__ t, int stage, int last, float* __restrict__ dout)
{
    extern __shared__ float sm[];
    float* Wp = sm;
    float* Wn = sm + HID * HID;
    float* Gp = sm + 2 * HID * HID;
    float* Gn = sm + 3 * HID * HID;
    float* as_ = sm + 4 * HID * HID;     // [8][HID]
    float* ns_ = as_ + 8 * HID;
    float* hs  = ns_ + 8 * HID;

    int tid = threadIdx.x;
    for (int i = tid; i < HID * HID; i += 256) {
        int j = i & 63, k = i >> 6;
        Wp[i] = Wpp_g[j * HID + k];
        Wn[i] = Wpn_g[j * HID + k];
        Gp[i] = Wposg[j * HID + k];
        Gn[i] = Wnegg[j * HID + k];
    }
    __syncthreads();

    int lane = tid & 31, warp = tid >> 5;
    float dt = (t[1] - t[0]) * 0.5f;     // / RK4_STEPS
    float2 bp = *(const float2*)&b_pos[2 * lane];
    float2 bn = *(const float2*)&b_neg[2 * lane];
    float bs0 = bpp[2 * lane] + bpn[2 * lane];
    float bs1 = bpp[2 * lane + 1] + bpn[2 * lane + 1];
    float2 ga = *(const float2*)&gamma[2 * lane];
    float2 be = *(const float2*)&beta[2 * lane];
    float* aw = as_ + warp * HID;
    float* nw = ns_ + warp * HID;
    float* hw = hs + warp * HID;
    bool final3 = (stage == 3) && last;

    for (int row = blockIdx.x * 8 + warp; row < N_NODES; row += gridDim.x * 8) {
        size_t off = (size_t)row * 32;
        float2 ap = ((const float2*)g_aggp)[off + lane];
        float2 an = ((const float2*)g_aggn)[off + lane];
        aw[2 * lane]     = ap.x + bp.x;
        aw[2 * lane + 1] = ap.y + bp.y;
        nw[2 * lane]     = an.x + bn.x;
        nw[2 * lane + 1] = an.y + bn.y;
        __syncwarp();
        float a0 = bs0, a1 = bs1;
        #pragma unroll
        for (int k = 0; k < HID; k++) {
            float akp = aw[k], akn = nw[k];
            float2 wp = *(const float2*)&Wp[k * HID + 2 * lane];
            float2 wn = *(const float2*)&Wn[k * HID + 2 * lane];
            a0 += akp * wp.x + akn * wn.x;
            a1 += akp * wp.y + akn * wn.y;
        }
        a0 = fminf(fmaxf(a0, -50.f), 50.f);
        a1 = fminf(fmaxf(a1, -50.f), 50.f);

        float2 h = ((const float2*)g_h)[off + lane];
        float hx, hy;
        if (stage == 0) {
            ((float2*)g_kacc)[off + lane] = make_float2(a0, a1);
            hx = h.x + 0.5f * dt * a0; hy = h.y + 0.5f * dt * a1;
        } else if (stage == 1) {
            float2 kv = ((float2*)g_kacc)[off + lane];
            kv.x += 2.f * a0; kv.y += 2.f * a1;
            ((float2*)g_kacc)[off + lane] = kv;
            hx = h.x + 0.5f * dt * a0; hy = h.y + 0.5f * dt * a1;
        } else if (stage == 2) {
            float2 kv = ((float2*)g_kacc)[off + lane];
            kv.x += 2.f * a0; kv.y += 2.f * a1;
            ((float2*)g_kacc)[off + lane] = kv;
            hx = h.x + dt * a0; hy = h.y + dt * a1;
        } else {
            float2 kv = ((float2*)g_kacc)[off + lane];
            float c = dt * (1.0f / 6.0f);
            hx = h.x + c * (kv.x + a0);
            hy = h.y + c * (kv.y + a1);
            ((float2*)g_h)[off + lane] = make_float2(hx, hy);
            if (last) ((float2*)dout)[off + lane] = make_float2(hx, hy);
        }

        if (!final3) {
            // LN(hx,hy) + dual GCN GEMM -> xp, xn (fp16)
            float s = hx + hy;
            #pragma unroll
            for (int o = 16; o; o >>= 1) s += __shfl_xor_sync(0xffffffffu, s, o);
            float mu = s * (1.0f / HID);
            float dx = hx - mu, dy = hy - mu;
            float q = dx * dx + dy * dy;
            #pragma unroll
            for (int o = 16; o; o >>= 1) q += __shfl_xor_sync(0xffffffffu, q, o);
            float rs = rsqrtf(q * (1.0f / HID) + LN_EPS);
            hw[2 * lane]     = dx * rs * ga.x + be.x;
            hw[2 * lane + 1] = dy * rs * ga.y + be.y;
            __syncwarp();
            float p0 = 0.f, p1 = 0.f, n0 = 0.f, n1 = 0.f;
            #pragma unroll
            for (int k = 0; k < HID; k++) {
                float hk = hw[k];
                float2 wp = *(const float2*)&Gp[k * HID + 2 * lane];
                float2 wn = *(const float2*)&Gn[k * HID + 2 * lane];
                p0 += hk * wp.x; p1 += hk * wp.y;
                n0 += hk * wn.x; n1 += hk * wn.y;
            }
            ((half2*)g_xp)[off + lane] = __floats2half2_rn(p0, p1);
            ((half2*)g_xn)[off + lane] = __floats2half2_rn(n0, n1);
        }
        __syncwarp();
    }
}

// ---------------- launch ----------------
extern "C" void kernel_launch(void* const* d_in, const int* in_sizes, int n_in,
                              void* d_out, int out_size)
{
    const float* x     = (const float*)d_in[0];
    const void*  eip   = d_in[1];
    const void*  ein   = d_in[2];
    const float* t     = (const float*)d_in[3];
    const float* W_enc = (const float*)d_in[4];
    const float* b_enc = (const float*)d_in[5];
    const float* W_pos = (const float*)d_in[6];
    const float* b_pos = (const float*)d_in[7];
    const float* W_neg = (const float*)d_in[8];
    const float* b_neg = (const float*)d_in[9];
    const float* Wpp   = (const float*)d_in[10];
    const float* bpp   = (const float*)d_in[11];
    const float* Wpn   = (const float*)d_in[12];
    const float* bpn   = (const float*)d_in[13];
    const float* gamma = (const float*)d_in[14];
    const float* beta  = (const float*)d_in[15];
    float* dout = (float*)d_out;

    cudaFuncSetAttribute(k_stage, cudaFuncAttributeMaxDynamicSharedMemorySize,
                         SM_STAGE_BYTES);

    const int nb_nodes  = (N_NODES + 255) / 256;
    const int nb_edges  = (int)((2LL * N_EDGES + 255) / 256);
    const int nb_gather = (2 * N_NODES + 7) / 8;   // 1 warp per (node, set)
    const int nb_gs     = 888;                     // grid-stride row kernels

    k_detect<<<1, 1>>>(eip);
    k_initdeg<<<nb_nodes, 256>>>();
    k_count<<<nb_edges, 256>>>(eip, ein);
    k_dinv<<<nb_nodes, 256>>>();
    k_scan<<<1, 1024>>>();
    k_reorder<<<nb_edges, 256>>>(eip, ein);
    k_encode<<<nb_gs, 256>>>(x, W_enc, b_enc);
    k_ln0<<<nb_gs, 256>>>(gamma, beta, W_pos, W_neg);

    for (int it = 0; it < 8; it++) {
        k_gather<<<nb_gather, 256>>>();
        int stage = it & 3;
        int last  = (it == 7) ? 1 : 0;
        k_stage<<<444, 256, SM_STAGE_BYTES>>>(
            b_pos, b_neg, Wpp, bpp, Wpn, bpn, gamma, beta,
            W_pos, W_neg, t, stage, last, dout);
    }
}